// round 1
// baseline (speedup 1.0000x reference)
#include <cuda_runtime.h>
#include <cuda_bf16.h>

// FHN IMEX dynamics, (4,4096,2048) fp32, 8 steps.
// One CTA per 2048-element row; 256 threads x 8 elements (two float4 loads).
// Inner loop uses packed f32x2 FMA (sm_103a) -> 7 packed FMAs + 2 scalar clips
// per 2 elements per step. w-clip omitted (provably inactive for 8 steps).

#define FHN_TAU 12.5f
#define FHN_THRESH 0.5f

typedef unsigned long long ull;

__device__ __forceinline__ ull pk2(float lo, float hi) {
    ull r; asm("mov.b64 %0, {%1, %2};" : "=l"(r) : "f"(lo), "f"(hi)); return r;
}
__device__ __forceinline__ float2 upk2(ull x) {
    float2 f; asm("mov.b64 {%0, %1}, %2;" : "=f"(f.x), "=f"(f.y) : "l"(x)); return f;
}
__device__ __forceinline__ ull fma2(ull a, ull b, ull c) {
    ull d; asm("fma.rn.f32x2 %0, %1, %2, %3;" : "=l"(d) : "l"(a), "l"(b), "l"(c)); return d;
}
__device__ __forceinline__ ull mul2(ull a, ull b) {
    ull d; asm("mul.rn.f32x2 %0, %1, %2;" : "=l"(d) : "l"(a), "l"(b)); return d;
}

__global__ __launch_bounds__(256, 4)
void fhn_kernel(const float* __restrict__ stim,
                const float* __restrict__ a_p,
                const float* __restrict__ b_p,
                const float* __restrict__ dt_p,
                const int*   __restrict__ ns_p,
                float* __restrict__ out,
                long long N, int writeV)
{
    const int  C    = 2048;
    const int  t    = threadIdx.x;
    const long long base = (long long)blockIdx.x * C;

    // ---- load 8 elements as two coalesced float4 ----
    const float4* s4 = reinterpret_cast<const float4*>(stim + base);
    float4 x0 = s4[t];        // elements 4t   .. 4t+3    (first half of row)
    float4 x1 = s4[t + 256];  // elements 1024+4t .. +3   (second half of row)

    // ---- row max(|x|) reduction ----
    float m = fmaxf(fmaxf(fmaxf(fabsf(x0.x), fabsf(x0.y)), fmaxf(fabsf(x0.z), fabsf(x0.w))),
                    fmaxf(fmaxf(fabsf(x1.x), fabsf(x1.y)), fmaxf(fabsf(x1.z), fabsf(x1.w))));
    #pragma unroll
    for (int o = 16; o > 0; o >>= 1)
        m = fmaxf(m, __shfl_xor_sync(0xffffffffu, m, o));
    __shared__ float wmax[8];
    if ((t & 31) == 0) wmax[t >> 5] = m;
    __syncthreads();
    m = wmax[0];
    #pragma unroll
    for (int i = 1; i < 8; ++i) m = fmaxf(m, wmax[i]);

    const float scale = fmaxf(m, 1e-6f);
    const float inv_scale = __fdividef(1.0f, scale);

    // ---- scalars / per-step constants ----
    const float a  = *a_p;
    const float b  = *b_p;
    const float dt = *dt_p;
    const int   n_steps = ns_p ? *ns_p : 8;

    const float alpha = dt / FHN_TAU;
    const float denom = 1.0f + alpha * b;
    const float k1 = 1.0f / denom;           // w' = k1*w + k2*v_next + k3
    const float k2 = alpha / denom;
    const float k3 = alpha * a / denom;
    const float c1 = 1.0f + dt;              // v_next = c1*v - (dt/3)*v^3 - dt*w + dt*I
    const float c3 = dt * (1.0f / 3.0f);

    const ull C1  = pk2(c1, c1);
    const ull NDT = pk2(-dt, -dt);
    const ull NC3 = pk2(-c3, -c3);
    const ull K1  = pk2(k1, k1);
    const ull K2  = pk2(k2, k2);
    const ull K3  = pk2(k3, k3);

    // ---- stimulus conditioning: I = (x/scale) * (0.1 + 0.9*sigmoid((|x|-0.5)*10)) ----
    float xs[8] = {x0.x, x0.y, x0.z, x0.w, x1.x, x1.y, x1.z, x1.w};
    float p[8];
    #pragma unroll
    for (int i = 0; i < 8; ++i) {
        float x  = xs[i];
        float ax = fabsf(x);
        float e  = __expf((FHN_THRESH - ax) * 10.0f);   // exp(-(|x|-0.5)*10)
        float g  = __fdividef(1.0f, 1.0f + e);          // sigmoid
        float I  = (x * inv_scale) * fmaf(0.9f, g, 0.1f);
        p[i] = dt * I;                                  // P = dt*I, loop-invariant
    }

    ull P[4], V[4], W[4];
    #pragma unroll
    for (int j = 0; j < 4; ++j) {
        P[j] = pk2(p[2 * j], p[2 * j + 1]);
        V[j] = 0ull;   // packed (0.0f, 0.0f)
        W[j] = 0ull;
    }

    // ---- IMEX loop ----
    for (int s = 0; s < n_steps; ++s) {
        #pragma unroll
        for (int j = 0; j < 4; ++j) {
            ull T  = mul2(V[j], V[j]);            // v^2
            ull S  = fma2(NDT, W[j], P[j]);       // dt*I - dt*w
            S      = fma2(C1, V[j], S);           // + (1+dt)*v
            ull M  = mul2(T, V[j]);               // v^3
            ull Vn = fma2(NC3, M, S);             // v_next (pre-clip)
            // w_next from PRE-CLIP v_next (matches reference); w never hits +/-3 in 8 steps
            W[j]   = fma2(K2, Vn, fma2(K1, W[j], K3));
            float2 vv = upk2(Vn);
            vv.x = fminf(fmaxf(vv.x, -3.0f), 3.0f);
            vv.y = fminf(fmaxf(vv.y, -3.0f), 3.0f);
            V[j] = pk2(vv.x, vv.y);
        }
    }

    // ---- outputs: response = v*scale at [0,N), v at [N,2N) ----
    float2 v01 = upk2(V[0]), v23 = upk2(V[1]), v45 = upk2(V[2]), v67 = upk2(V[3]);

    float4* r4 = reinterpret_cast<float4*>(out + base);
    r4[t]       = make_float4(v01.x * scale, v01.y * scale, v23.x * scale, v23.y * scale);
    r4[t + 256] = make_float4(v45.x * scale, v45.y * scale, v67.x * scale, v67.y * scale);

    if (writeV) {
        float4* v4 = reinterpret_cast<float4*>(out + N + base);
        v4[t]       = make_float4(v01.x, v01.y, v23.x, v23.y);
        v4[t + 256] = make_float4(v45.x, v45.y, v67.x, v67.y);
    }
}

extern "C" void kernel_launch(void* const* d_in, const int* in_sizes, int n_in,
                              void* d_out, int out_size)
{
    const float* stim = (const float*)d_in[0];
    const float* a    = (const float*)d_in[1];
    const float* b    = (const float*)d_in[2];
    const float* dt   = (const float*)d_in[3];
    const int*   ns   = (n_in > 4) ? (const int*)d_in[4] : nullptr;

    long long N = (long long)in_sizes[0];          // 4*4096*2048 = 33,554,432
    int rows = (int)(N / 2048);                    // 16384 CTAs
    int writeV = ((long long)out_size >= 2 * N) ? 1 : 0;

    fhn_kernel<<<rows, 256>>>(stim, a, b, dt, ns, (float*)d_out, N, writeV);
}

// round 2
// speedup vs baseline: 1.1825x; 1.1825x over previous
#include <cuda_runtime.h>
#include <cuda_bf16.h>

// FHN IMEX dynamics, (4,4096,2048) fp32, 8 steps.
// One CTA per 2048-element row; 256 threads x 8 elements.
// w-recurrence folded into s = P - dt*w  ->  5 packed f32x2 FMA-pipe ops +
// 4 scalar FMNMX per 2 elements per step. No pack/unpack MOVs (union aliasing).

#define FHN_TAU 12.5f
#define FHN_THRESH 0.5f

typedef unsigned long long ull;

union UF { ull u; float2 f; };

__device__ __forceinline__ ull pk2(float lo, float hi) {
    UF r; r.f.x = lo; r.f.y = hi; return r.u;
}
__device__ __forceinline__ ull fma2(ull a, ull b, ull c) {
    ull d; asm("fma.rn.f32x2 %0, %1, %2, %3;" : "=l"(d) : "l"(a), "l"(b), "l"(c)); return d;
}
__device__ __forceinline__ ull mul2(ull a, ull b) {
    ull d; asm("mul.rn.f32x2 %0, %1, %2;" : "=l"(d) : "l"(a), "l"(b)); return d;
}
__device__ __forceinline__ ull clip2(ull x) {
    UF v; v.u = x;
    v.f.x = fminf(fmaxf(v.f.x, -3.0f), 3.0f);
    v.f.y = fminf(fmaxf(v.f.y, -3.0f), 3.0f);
    return v.u;
}

__global__ __launch_bounds__(256, 5)
void fhn_kernel(const float* __restrict__ stim,
                const float* __restrict__ a_p,
                const float* __restrict__ b_p,
                const float* __restrict__ dt_p,
                const int*   __restrict__ ns_p,
                float* __restrict__ out,
                long long N, int writeV)
{
    const int  C    = 2048;
    const int  t    = threadIdx.x;
    const long long base = (long long)blockIdx.x * C;

    // ---- load 8 elements as two coalesced float4 ----
    const float4* s4 = reinterpret_cast<const float4*>(stim + base);
    float4 x0 = s4[t];        // first half of row
    float4 x1 = s4[t + 256];  // second half of row

    // ---- row max(|x|) reduction ----
    float m = fmaxf(fmaxf(fmaxf(fabsf(x0.x), fabsf(x0.y)), fmaxf(fabsf(x0.z), fabsf(x0.w))),
                    fmaxf(fmaxf(fabsf(x1.x), fabsf(x1.y)), fmaxf(fabsf(x1.z), fabsf(x1.w))));
    #pragma unroll
    for (int o = 16; o > 0; o >>= 1)
        m = fmaxf(m, __shfl_xor_sync(0xffffffffu, m, o));
    __shared__ float wmax[8];
    if ((t & 31) == 0) wmax[t >> 5] = m;
    __syncthreads();
    m = wmax[0];
    #pragma unroll
    for (int i = 1; i < 8; ++i) m = fmaxf(m, wmax[i]);

    const float scale = fmaxf(m, 1e-6f);
    const float inv_scale = __fdividef(1.0f, scale);

    // ---- scalars / per-step constants ----
    const float a  = *a_p;
    const float b  = *b_p;
    const float dt = *dt_p;
    const int   n_steps = ns_p ? *ns_p : 8;

    const float alpha = dt / FHN_TAU;
    const float denom = 1.0f + alpha * b;
    const float k1 = 1.0f / denom;
    const float k2 = alpha / denom;
    const float k3 = alpha * a / denom;
    const float c1 = 1.0f + dt;              // v_pre = v*(c1 - c3*v^2) + s
    const float c3 = dt * (1.0f / 3.0f);

    // s-recurrence: s = P - dt*w;  s' = k1*s + NCK*v_pre + P2
    const float omk1 = 1.0f - k1;
    const float ndk3 = -dt * k3;
    const float nck  = -dt * k2;

    const ull C1  = pk2(c1, c1);
    const ull NC3 = pk2(-c3, -c3);
    const ull K1  = pk2(k1, k1);
    const ull NCK = pk2(nck, nck);

    // ---- stimulus conditioning:
    //   I = (x/scale)*(0.1 + 0.9*sigmoid((|x|-0.5)*10));  P = dt*I
    //   P2 = (1-k1)*P - dt*k3   (per-element loop constant);  s0 = P
    const float di = dt * inv_scale;
    float xs[8] = {x0.x, x0.y, x0.z, x0.w, x1.x, x1.y, x1.z, x1.w};
    float p[8], p2[8];
    #pragma unroll
    for (int i = 0; i < 8; ++i) {
        float x  = xs[i];
        float ax = fabsf(x);
        float e  = __expf(fmaf(-10.0f, ax, 5.0f));      // exp(-(|x|-0.5)*10)
        float g  = __fdividef(1.0f, 1.0f + e);          // sigmoid
        float P  = (di * x) * fmaf(0.9f, g, 0.1f);
        p[i]  = P;
        p2[i] = fmaf(omk1, P, ndk3);
    }

    ull P2[4], V[4], S[4];
    #pragma unroll
    for (int j = 0; j < 4; ++j) {
        S[j]  = pk2(p[2 * j], p[2 * j + 1]);            // s0 = P  (w0 = 0)
        P2[j] = pk2(p2[2 * j], p2[2 * j + 1]);
        V[j]  = 0ull;
    }

    // ---- IMEX loop: 5 packed FMA-pipe ops + clip per pair per step ----
    for (int s = 0; s < n_steps; ++s) {
        #pragma unroll
        for (int j = 0; j < 4; ++j) {
            ull T  = mul2(V[j], V[j]);             // v^2
            ull R  = fma2(NC3, T, C1);             // c1 - c3*v^2
            ull Vp = fma2(R, V[j], S[j]);          // v_pre
            S[j]   = fma2(K1, S[j], fma2(NCK, Vp, P2[j]));
            V[j]   = clip2(Vp);
        }
    }

    // ---- outputs: response = v*scale at [0,N), v at [N,2N) ----
    const ull SC = pk2(scale, scale);
    UF r0, r1, r2, r3, v0, v1, v2, v3;
    v0.u = V[0]; v1.u = V[1]; v2.u = V[2]; v3.u = V[3];
    r0.u = mul2(V[0], SC); r1.u = mul2(V[1], SC);
    r2.u = mul2(V[2], SC); r3.u = mul2(V[3], SC);

    float4* o4 = reinterpret_cast<float4*>(out + base);
    o4[t]       = make_float4(r0.f.x, r0.f.y, r1.f.x, r1.f.y);
    o4[t + 256] = make_float4(r2.f.x, r2.f.y, r3.f.x, r3.f.y);

    if (writeV) {
        float4* v4 = reinterpret_cast<float4*>(out + N + base);
        v4[t]       = make_float4(v0.f.x, v0.f.y, v1.f.x, v1.f.y);
        v4[t + 256] = make_float4(v2.f.x, v2.f.y, v3.f.x, v3.f.y);
    }
}

extern "C" void kernel_launch(void* const* d_in, const int* in_sizes, int n_in,
                              void* d_out, int out_size)
{
    const float* stim = (const float*)d_in[0];
    const float* a    = (const float*)d_in[1];
    const float* b    = (const float*)d_in[2];
    const float* dt   = (const float*)d_in[3];
    const int*   ns   = (n_in > 4) ? (const int*)d_in[4] : nullptr;

    long long N = (long long)in_sizes[0];          // 33,554,432
    int rows = (int)(N / 2048);                    // 16384 CTAs
    int writeV = ((long long)out_size >= 2 * N) ? 1 : 0;

    fhn_kernel<<<rows, 256>>>(stim, a, b, dt, ns, (float*)d_out, N, writeV);
}